// round 12
// baseline (speedup 1.0000x reference)
#include <cuda_runtime.h>
#include <cuda_bf16.h>

// WaveletTransformer_867583394320 — FINAL (machine floor; converged).
//
// Math: 4-level Haar DWT immediately inverted by its exact IDWT with the
// same detail coefficients. Orthogonal perfect reconstruction: one level
// composes to x * 2c^2 (c = fp32(1/√2)), full pipeline = x * (2c^2)^4 =
// x * (1 - ~2.4e-7). Measured rel_err 9.571855e-8 (threshold 1e-3).
// => The problem is an identity; optimal kernel is a 256 MiB D2D copy.
//
// Measurement record (four configurations, ten benches):
//   R1  SM float4 grid-stride copy            6361 GB/s   84.5us
//   R2  SM + __ldcs/__stcs + 4x MLP batching  6261 GB/s   84.7us
//   R3-R8,R10  single CE memcpy node:
//       {84.0, 82.4, 84.5, 84.0, 83.0, 84.0, 82.7}us (mean 83.5, sigma 0.8)
//   R9  dual-CE fork-join (2 parallel memcpy nodes): 83.4us — NEUTRAL,
//       falsifying "single CE engine-limited".
// All four paths sit at ~6.4 TB/s combined R+W = ~80% of the 8 TB/s spec:
// the HBM3e mixed read/write-turnaround floor, path-independent (SM ≡ CE ≡
// 2xCE; LDG.cv ≡ TMA per B300_MICROARCH.md). Device time 512 MiB / 6.4 TB/s
// ≈ 77us; residual ~6us is harness graph-replay overhead.
//
// Closed levers: traffic reduction (out==in, poisoned d_out, incompressible
// -> 512 MiB irreducible); inter-replay L2 persistence (carveout trips the
// harness device-limit guard; no LRU reuse on a 256MB>126MB cyclic stream
// without it); engine concurrency (measured neutral); streaming/TMA/write-
// through paths (measured or documented at the same cap).
//
// Final form: single memcpy node — simplest graph, lowest variance, at the
// hardware floor.

extern "C" void kernel_launch(void* const* d_in, const int* in_sizes, int n_in,
                              void* d_out, int out_size) {
    const float* x = (const float*)d_in[0];
    float* out = (float*)d_out;
    size_t bytes = (size_t)out_size * sizeof(float);
    // Async D2D on the capture (default) stream: captured as a single memcpy
    // node executed by the copy engine. No allocation, no sync — capture-legal.
    cudaMemcpyAsync(out, x, bytes, cudaMemcpyDeviceToDevice, 0);
}

// round 13
// speedup vs baseline: 1.0581x; 1.0581x over previous
#include <cuda_runtime.h>
#include <cuda_bf16.h>

// WaveletTransformer_867583394320 — FINAL (machine floor; converged).
//
// Math: 4-level Haar DWT immediately inverted by its exact IDWT with the
// same detail coefficients. Orthogonal perfect reconstruction: one level
// composes to x * 2c^2 (c = fp32(1/√2)), full pipeline = x * (2c^2)^4 =
// x * (1 - ~2.4e-7). Measured rel_err 9.571855e-8 (threshold 1e-3).
// => The problem is an identity; optimal kernel is a 256 MiB D2D copy.
//
// Measurement record (four configurations, eleven benches):
//   R1  SM float4 grid-stride copy            6361 GB/s   84.5us
//   R2  SM + __ldcs/__stcs + 4x MLP batching  6261 GB/s   84.7us
//   R3-R8,R10,R11  single CE memcpy node (identical code):
//       {84.0, 82.4, 84.5, 84.0, 83.0, 84.0, 82.7, 88.6}us
//       (88.6 = environmental outlier — DVFS/container jitter on that hold;
//        seven prior samples: mean 83.5, sigma 0.8)
//   R9  dual-CE fork-join (2 parallel memcpy nodes): 83.4us — NEUTRAL,
//       falsifying "single CE engine-limited".
// All four paths sit at ~6.4 TB/s combined R+W = ~80% of the 8 TB/s spec:
// the HBM3e mixed read/write-turnaround floor, path-independent (SM ≡ CE ≡
// 2xCE; LDG.cv ≡ TMA per B300_MICROARCH.md). Device time 512 MiB / 6.4 TB/s
// ≈ 77us; residual is harness graph-replay overhead + environment.
//
// Closed levers: traffic reduction (out==in, poisoned d_out, incompressible
// -> 512 MiB irreducible); inter-replay L2 persistence (carveout trips the
// harness device-limit guard; no LRU reuse on a 256MB>126MB cyclic stream
// without it); engine concurrency (measured neutral); streaming/TMA/write-
// through paths (measured or documented at the same cap).
//
// Final form: single memcpy node — simplest graph, minimum structure exposed
// to launch jitter, at the hardware floor.

extern "C" void kernel_launch(void* const* d_in, const int* in_sizes, int n_in,
                              void* d_out, int out_size) {
    const float* x = (const float*)d_in[0];
    float* out = (float*)d_out;
    size_t bytes = (size_t)out_size * sizeof(float);
    // Async D2D on the capture (default) stream: captured as a single memcpy
    // node executed by the copy engine. No allocation, no sync — capture-legal.
    cudaMemcpyAsync(out, x, bytes, cudaMemcpyDeviceToDevice, 0);
}

// round 14
// speedup vs baseline: 1.0609x; 1.0027x over previous
#include <cuda_runtime.h>
#include <cuda_bf16.h>

// WaveletTransformer_867583394320 — FINAL (machine floor; converged).
//
// Math: 4-level Haar DWT immediately inverted by its exact IDWT with the
// same detail coefficients. Orthogonal perfect reconstruction: one level
// composes to x * 2c^2 (c = fp32(1/√2)), full pipeline = x * (2c^2)^4 =
// x * (1 - ~2.4e-7). Measured rel_err 9.571855e-8 (threshold 1e-3).
// => The problem is an identity; optimal kernel is a 256 MiB D2D copy.
//
// Measurement record (four configurations, twelve benches):
//   R1  SM float4 grid-stride copy            6361 GB/s   84.5us
//   R2  SM + __ldcs/__stcs + 4x MLP batching  6261 GB/s   84.7us
//   R3-R12  single CE memcpy node (identical code):
//       {84.0, 82.4, 84.5, 84.0, 83.0, 84.0, 82.7, 88.6, 83.7}us
//       mean ~83.6, sigma ~0.8 (88.6 = one environmental/DVFS outlier,
//       confirmed by the immediate return to band)
//   R9  dual-CE fork-join (2 parallel memcpy nodes): 83.4us — NEUTRAL,
//       falsifying "single CE engine-limited".
// All four paths sit at ~6.4 TB/s combined R+W = ~80% of the 8 TB/s spec:
// the HBM3e mixed read/write-turnaround floor, path-independent (SM ≡ CE ≡
// 2xCE; LDG.cv ≡ TMA per B300_MICROARCH.md). Device time 512 MiB / 6.4 TB/s
// ≈ 77us; residual ~6us is harness graph-replay overhead.
//
// Closed levers: traffic reduction (out==in, poisoned d_out, incompressible
// -> 512 MiB irreducible); inter-replay L2 persistence (carveout trips the
// harness device-limit guard; no LRU reuse on a 256MB>126MB cyclic stream
// without it); engine concurrency (measured neutral); streaming/TMA/write-
// through paths (measured or documented at the same cap).
//
// Final form: single memcpy node — simplest graph, minimum structure exposed
// to launch jitter, at the hardware floor.

extern "C" void kernel_launch(void* const* d_in, const int* in_sizes, int n_in,
                              void* d_out, int out_size) {
    const float* x = (const float*)d_in[0];
    float* out = (float*)d_out;
    size_t bytes = (size_t)out_size * sizeof(float);
    // Async D2D on the capture (default) stream: captured as a single memcpy
    // node executed by the copy engine. No allocation, no sync — capture-legal.
    cudaMemcpyAsync(out, x, bytes, cudaMemcpyDeviceToDevice, 0);
}